// round 1
// baseline (speedup 1.0000x reference)
#include <cuda_runtime.h>

// Cheb_conv: out[b,o,m,t] = sum_{k,c,n} T[k,n,m] x[b,c,n,t] Theta[k,c,o]
// b=64, c=o=32, n=m=24, t=512, K=3.
// T0=I, T1=L, T2=2L^2-I  =>
//   out = (Th0-Th2)^T X + Th1^T (X L) + 2 Th2^T (X L^2)   per (b,t) slice X[c,n].

#define NV 24
#define NC 32
#define NO 32
#define NT 512
#define NB 64
#define TT 32

// Precomputed operators (written by prep kernel every launch; deterministic).
__device__ float2 g_LL[NV * NV];   // (L[n][m], L2[n][m])
__device__ float  g_Mt[NO * 96];   // Mt[o][j]: j in [0,32)=Th0-Th2, [32,64)=Th1, [64,96)=2*Th2 (indexed by c)

__global__ void cheb_prep(const float* __restrict__ adj,
                          const float* __restrict__ Theta) {
    __shared__ float dinv[NV];
    __shared__ float L[NV][NV];
    int tid = threadIdx.x;

    if (tid < NV) {
        float s = 0.f;
        #pragma unroll
        for (int j = 0; j < NV; j++) s += adj[tid * NV + j];
        dinv[tid] = (s > 0.f) ? rsqrtf(s) : 0.f;
    }
    __syncthreads();

    for (int idx = tid; idx < NV * NV; idx += blockDim.x) {
        int i = idx / NV, j = idx % NV;
        // L[i][j] = adj[j][i] * dinv[i] * dinv[j]
        L[i][j] = adj[j * NV + i] * dinv[i] * dinv[j];
    }
    __syncthreads();

    for (int idx = tid; idx < NV * NV; idx += blockDim.x) {
        int i = idx / NV, j = idx % NV;
        float s = 0.f;
        #pragma unroll
        for (int q = 0; q < NV; q++) s += L[i][q] * L[q][j];
        g_LL[idx] = make_float2(L[i][j], s);   // (L, L^2)
    }

    for (int idx = tid; idx < NO * 96; idx += blockDim.x) {
        int o = idx / 96, j = idx % 96;
        int c = j & 31, blk = j >> 5;
        float val;
        if (blk == 0)      val = Theta[(0 * NC + c) * NO + o] - Theta[(2 * NC + c) * NO + o];
        else if (blk == 1) val = Theta[(1 * NC + c) * NO + o];
        else               val = 2.f * Theta[(2 * NC + c) * NO + o];
        g_Mt[idx] = val;
    }
}

// Block: (t-chunk of 32, m-group of 8, b). 256 threads = 8 warps.
// warp -> m, lane -> t. X tile [32 c][24 n][32 t] in dynamic smem (98.3 KB).
__global__ void __launch_bounds__(256, 2)
cheb_main(const float* __restrict__ x, float* __restrict__ out) {
    extern __shared__ float smem[];
    float*  Xs  = smem;                               // [NC][NV][TT]
    float2* LLs = (float2*)(smem + NC * NV * TT);     // [NV*NV]

    int tid  = threadIdx.x;
    int lane = tid & 31;
    int warp = tid >> 5;
    int b    = blockIdx.z;
    int t0   = blockIdx.x * TT;
    int m    = blockIdx.y * 8 + warp;

    // ---- Load X tile (coalesced float4) ----
    const float4* xg  = (const float4*)(x + ((size_t)b * NC * NV) * NT + t0);
    float4*       Xs4 = (float4*)Xs;
    #pragma unroll 4
    for (int i = tid; i < NC * NV * (TT / 4); i += 256) {
        int row = i >> 3, q = i & 7;                  // row = c*24+n
        Xs4[i] = xg[row * (NT / 4) + q];
    }
    for (int i = tid; i < NV * NV; i += 256) LLs[i] = g_LL[i];
    __syncthreads();

    // ---- Stage A: w[c] = (X L)[c,m,t], v[c] = (X L^2)[c,m,t] ----
    float w[NC], v[NC];
    #pragma unroll
    for (int c = 0; c < NC; c++) { w[c] = 0.f; v[c] = 0.f; }

    const float* Xl = Xs + lane;
    for (int n = 0; n < NV; n++) {
        float2 ll = LLs[n * NV + m];                  // broadcast (uniform per warp)
        #pragma unroll
        for (int c = 0; c < NC; c++) {
            float xn = Xl[(c * NV + n) * TT];
            w[c] = fmaf(xn, ll.x, w[c]);
            v[c] = fmaf(xn, ll.y, v[c]);
        }
    }

    float xm[NC];
    #pragma unroll
    for (int c = 0; c < NC; c++) xm[c] = Xl[(c * NV + m) * TT];

    // ---- Stage B: out[o] = sum_c M0[c,o] xm[c] + M1[c,o] w[c] + M2[c,o] v[c] ----
    float* outp = out + (((size_t)b * NO) * NV + m) * NT + t0 + lane;
    const float4* Mt4 = (const float4*)g_Mt;
    for (int o = 0; o < NO; o++) {
        float acca = 0.f, accb = 0.f, accc = 0.f;
        #pragma unroll
        for (int q = 0; q < 8; q++) {
            float4 a  = __ldg(&Mt4[o * 24 + q]);
            float4 bq = __ldg(&Mt4[o * 24 + 8 + q]);
            float4 cq = __ldg(&Mt4[o * 24 + 16 + q]);
            acca += a.x  * xm[4 * q] + a.y  * xm[4 * q + 1] + a.z  * xm[4 * q + 2] + a.w  * xm[4 * q + 3];
            accb += bq.x * w[4 * q]  + bq.y * w[4 * q + 1]  + bq.z * w[4 * q + 2]  + bq.w * w[4 * q + 3];
            accc += cq.x * v[4 * q]  + cq.y * v[4 * q + 1]  + cq.z * v[4 * q + 2]  + cq.w * v[4 * q + 3];
        }
        outp[(size_t)o * NV * NT] = acca + accb + accc;
    }
}

extern "C" void kernel_launch(void* const* d_in, const int* in_sizes, int n_in,
                              void* d_out, int out_size) {
    const float* x     = (const float*)d_in[0];   // (64,32,24,512)
    const float* adj   = (const float*)d_in[1];   // (24,24)
    const float* Theta = (const float*)d_in[2];   // (3,32,32)
    float* out = (float*)d_out;                   // (64,32,24,512)

    size_t smem = (size_t)NC * NV * TT * sizeof(float) + (size_t)NV * NV * sizeof(float2); // 102912 B
    cudaFuncSetAttribute(cheb_main, cudaFuncAttributeMaxDynamicSharedMemorySize, (int)smem);

    cheb_prep<<<1, 128>>>(adj, Theta);

    dim3 grid(NT / TT, 3, NB);   // 16 t-chunks, 3 m-groups, 64 b
    cheb_main<<<grid, 256, smem>>>(x, out);
}

// round 2
// speedup vs baseline: 1.7482x; 1.7482x over previous
#include <cuda_runtime.h>

// Cheb_conv: out[b,o,m,t] = sum_{k,c,n} T[k,n,m] x[b,c,n,t] Theta[k,c,o]
// b=64, c=o=32, n=m=24, t=512, K=3.
// T0=I, T1=L, T2=2L^2-I  =>
//   out = (Th0-Th2)^T X + Th1^T (X L) + 2 Th2^T (X L^2)   per (b,t) slice X[c,n].

#define NV 24
#define NC 32
#define NO 32
#define NT 512
#define NB 64
#define TT 32

// Precomputed operators (written by prep kernel every launch; deterministic).
__device__ float2 g_LL[NV * NV];   // (L[n][m], L2[n][m])
__device__ float  g_Mt[NO * 96];   // Mt[o][j]: j in [0,32)=Th0-Th2, [32,64)=Th1, [64,96)=2*Th2 (indexed by c)

__global__ void cheb_prep(const float* __restrict__ adj,
                          const float* __restrict__ Theta) {
    __shared__ float dinv[NV];
    __shared__ float L[NV][NV];
    int tid = threadIdx.x;

    if (tid < NV) {
        float s = 0.f;
        #pragma unroll
        for (int j = 0; j < NV; j++) s += adj[tid * NV + j];
        dinv[tid] = (s > 0.f) ? rsqrtf(s) : 0.f;
    }
    __syncthreads();

    for (int idx = tid; idx < NV * NV; idx += blockDim.x) {
        int i = idx / NV, j = idx % NV;
        // L[i][j] = adj[j][i] * dinv[i] * dinv[j]
        L[i][j] = adj[j * NV + i] * dinv[i] * dinv[j];
    }
    __syncthreads();

    for (int idx = tid; idx < NV * NV; idx += blockDim.x) {
        int i = idx / NV, j = idx % NV;
        float s = 0.f;
        #pragma unroll
        for (int q = 0; q < NV; q++) s += L[i][q] * L[q][j];
        g_LL[idx] = make_float2(L[i][j], s);   // (L, L^2)
    }

    for (int idx = tid; idx < NO * 96; idx += blockDim.x) {
        int o = idx / 96, j = idx % 96;
        int c = j & 31, blk = j >> 5;
        float val;
        if (blk == 0)      val = Theta[(0 * NC + c) * NO + o] - Theta[(2 * NC + c) * NO + o];
        else if (blk == 1) val = Theta[(1 * NC + c) * NO + o];
        else               val = 2.f * Theta[(2 * NC + c) * NO + o];
        g_Mt[idx] = val;
    }
}

// Block: (t-chunk of 32, m-group of 8, b). 256 threads = 8 warps.
// warp -> m, lane -> t.
// Smem: X tile [32 c][24 n][32 t] (96 KB) + M [32 o][96 j] (12 KB) = 110.6 KB
// -> 2 blocks/SM. Stage-B weight reads are broadcast LDS.128 (1 wf each),
// replacing the LDG stream that hit the 4-cyc LSU dispatch floor in R1.
__global__ void __launch_bounds__(256, 2)
cheb_main(const float* __restrict__ x, float* __restrict__ out) {
    extern __shared__ float smem[];
    float* Xs = smem;                     // [NC][NV][TT] = 24576 floats
    float* Ms = smem + NC * NV * TT;      // [NO][96]     = 3072 floats

    int tid  = threadIdx.x;
    int lane = tid & 31;
    int warp = tid >> 5;
    int b    = blockIdx.z;
    int t0   = blockIdx.x * TT;
    int m    = blockIdx.y * 8 + warp;

    // ---- Load X tile (coalesced float4) ----
    const float4* xg  = (const float4*)(x + ((size_t)b * NC * NV) * NT + t0);
    float4*       Xs4 = (float4*)Xs;
    #pragma unroll 4
    for (int i = tid; i < NC * NV * (TT / 4); i += 256) {
        int row = i >> 3, q = i & 7;                  // row = c*24+n
        Xs4[i] = xg[row * (NT / 4) + q];
    }
    // ---- Stage M into smem (768 float4, 3 per thread) ----
    {
        float4*       Ms4w = (float4*)Ms;
        const float4* gM4  = (const float4*)g_Mt;
        #pragma unroll
        for (int i = tid; i < NO * 24; i += 256) Ms4w[i] = gM4[i];
    }
    __syncthreads();

    // ---- Stage A: w[c] = (X L)[c,m,t], v[c] = (X L^2)[c,m,t] ----
    float w[NC], v[NC];
    #pragma unroll
    for (int c = 0; c < NC; c++) { w[c] = 0.f; v[c] = 0.f; }

    const float* Xl = Xs + lane;
    for (int n = 0; n < NV; n++) {
        float2 ll = __ldg(&g_LL[n * NV + m]);         // uniform broadcast LDG.64 (24 total)
        #pragma unroll
        for (int c = 0; c < NC; c++) {
            float xn = Xl[(c * NV + n) * TT];
            w[c] = fmaf(xn, ll.x, w[c]);
            v[c] = fmaf(xn, ll.y, v[c]);
        }
    }

    float xm[NC];
    #pragma unroll
    for (int c = 0; c < NC; c++) xm[c] = Xl[(c * NV + m) * TT];

    // ---- Stage B: out[o] = sum_c M0[c,o] xm[c] + M1[c,o] w[c] + M2[c,o] v[c] ----
    // M reads: broadcast LDS.128 from smem (uniform per warp -> 1 wavefront each)
    float* outp = out + (((size_t)b * NO) * NV + m) * NT + t0 + lane;
    const float4* Mt4 = (const float4*)Ms;
    for (int o = 0; o < NO; o++) {
        float acca = 0.f, accb = 0.f, accc = 0.f;
        #pragma unroll
        for (int q = 0; q < 8; q++) {
            float4 a  = Mt4[o * 24 + q];
            float4 bq = Mt4[o * 24 + 8 + q];
            float4 cq = Mt4[o * 24 + 16 + q];
            acca = fmaf(a.x,  xm[4 * q],     acca); acca = fmaf(a.y,  xm[4 * q + 1], acca);
            acca = fmaf(a.z,  xm[4 * q + 2], acca); acca = fmaf(a.w,  xm[4 * q + 3], acca);
            accb = fmaf(bq.x, w[4 * q],      accb); accb = fmaf(bq.y, w[4 * q + 1],  accb);
            accb = fmaf(bq.z, w[4 * q + 2],  accb); accb = fmaf(bq.w, w[4 * q + 3],  accb);
            accc = fmaf(cq.x, v[4 * q],      accc); accc = fmaf(cq.y, v[4 * q + 1],  accc);
            accc = fmaf(cq.z, v[4 * q + 2],  accc); accc = fmaf(cq.w, v[4 * q + 3],  accc);
        }
        outp[(size_t)o * NV * NT] = acca + accb + accc;
    }
}

extern "C" void kernel_launch(void* const* d_in, const int* in_sizes, int n_in,
                              void* d_out, int out_size) {
    const float* x     = (const float*)d_in[0];   // (64,32,24,512)
    const float* adj   = (const float*)d_in[1];   // (24,24)
    const float* Theta = (const float*)d_in[2];   // (3,32,32)
    float* out = (float*)d_out;                   // (64,32,24,512)

    size_t smem = ((size_t)NC * NV * TT + (size_t)NO * 96) * sizeof(float); // 110592 B
    cudaFuncSetAttribute(cheb_main, cudaFuncAttributeMaxDynamicSharedMemorySize, (int)smem);

    cheb_prep<<<1, 128>>>(adj, Theta);

    dim3 grid(NT / TT, 3, NB);   // 16 t-chunks, 3 m-groups, 64 b
    cheb_main<<<grid, 256, smem>>>(x, out);
}

// round 3
// speedup vs baseline: 2.2892x; 1.3095x over previous
#include <cuda_runtime.h>

// Cheb_conv: out[b,o,m,t] = sum_{k,c,n} T[k,n,m] x[b,c,n,t] Theta[k,c,o]
// b=64, c=o=32, n=m=24, t=512, K=3.
// T0=I, T1=L, T2=2L^2-I  =>
//   out = (Th0-Th2)^T X + Th1^T (X L) + 2 Th2^T (X L^2)   per (b,t) slice X[c,n].
//
// R3: packed fp32 math via fma.rn.f32x2 (SASS FFMA2) to halve the FFMA issue
// floor. Thread covers a t-pair; Stage A accumulates (t,t+1) pairs with L/L^2
// pre-duplicated as (L,L | L2,L2); Stage B pairs adjacent o with M stored as
// (o,o+1) float2 pairs; x-side scalars duplicated via mov.b64 (amortized 16x).

#define NV 24
#define NC 32
#define NO 32
#define NT 512
#define NB 64
#define TT 64          // t per block (lane -> t-pair)
#define CCH 4          // c per chunk
#define NCHUNK (NC / CCH)

typedef unsigned long long ull_t;

__device__ __forceinline__ ull_t ffma2(ull_t a, ull_t b, ull_t c) {
    ull_t d;
    asm("fma.rn.f32x2 %0, %1, %2, %3;" : "=l"(d) : "l"(a), "l"(b), "l"(c));
    return d;
}
__device__ __forceinline__ ull_t pack2(float x, float y) {
    ull_t d;
    asm("mov.b64 %0, {%1, %2};" : "=l"(d) : "f"(x), "f"(y));
    return d;
}
__device__ __forceinline__ float2 unpack2(ull_t v) {
    float2 r;
    asm("mov.b64 {%0, %1}, %2;" : "=f"(r.x), "=f"(r.y) : "l"(v));
    return r;
}

// Precomputed operators (written by prep kernel every launch; deterministic).
__device__ float4 g_LLd[NV * NV];       // [n][m] = (L, L, L2, L2)
__device__ float2 g_M2[96 * (NO / 2)];  // [blk*32+c][oo] = (coef[2oo], coef[2oo+1])
                                        // blk0 = Th0-Th2, blk1 = Th1, blk2 = 2*Th2

__global__ void cheb_prep(const float* __restrict__ adj,
                          const float* __restrict__ Theta) {
    __shared__ float dinv[NV];
    __shared__ float L[NV][NV];
    int tid = threadIdx.x;

    if (tid < NV) {
        float s = 0.f;
        #pragma unroll
        for (int j = 0; j < NV; j++) s += adj[tid * NV + j];
        dinv[tid] = (s > 0.f) ? rsqrtf(s) : 0.f;
    }
    __syncthreads();

    for (int idx = tid; idx < NV * NV; idx += blockDim.x) {
        int i = idx / NV, j = idx % NV;
        L[i][j] = adj[j * NV + i] * dinv[i] * dinv[j];
    }
    __syncthreads();

    for (int idx = tid; idx < NV * NV; idx += blockDim.x) {
        int i = idx / NV, j = idx % NV;
        float s = 0.f;
        #pragma unroll
        for (int q = 0; q < NV; q++) s += L[i][q] * L[q][j];
        g_LLd[idx] = make_float4(L[i][j], L[i][j], s, s);
    }

    for (int idx = tid; idx < 96 * (NO / 2); idx += blockDim.x) {
        int j = idx / (NO / 2), oo = idx % (NO / 2);
        int blk = j >> 5, c = j & 31;
        float a, b;
        if (blk == 0) {
            a = Theta[(0 * NC + c) * NO + 2 * oo]     - Theta[(2 * NC + c) * NO + 2 * oo];
            b = Theta[(0 * NC + c) * NO + 2 * oo + 1] - Theta[(2 * NC + c) * NO + 2 * oo + 1];
        } else if (blk == 1) {
            a = Theta[(1 * NC + c) * NO + 2 * oo];
            b = Theta[(1 * NC + c) * NO + 2 * oo + 1];
        } else {
            a = 2.f * Theta[(2 * NC + c) * NO + 2 * oo];
            b = 2.f * Theta[(2 * NC + c) * NO + 2 * oo + 1];
        }
        g_M2[idx] = make_float2(a, b);
    }
}

// Block: (t-chunk of 64, m-group of 8, b). 256 threads = 8 warps.
// warp -> m, lane -> t-pair. X staged per 4-c chunk (24.6 KB); LL dup (9 KB);
// M o-paired (12 KB). Static smem 46 KB -> 2 blocks/SM.
__global__ void __launch_bounds__(256, 2)
cheb_main(const float* __restrict__ x, float* __restrict__ out) {
    __shared__ float  Xs[CCH * NV * TT];   // [4 c][24 n][64 t]
    __shared__ float4 LLs[NV * NV];        // [n][m] dup pairs
    __shared__ float2 Ms[96 * (NO / 2)];   // o-paired weights

    int tid  = threadIdx.x;
    int lane = tid & 31;
    int warp = tid >> 5;
    int b    = blockIdx.z;
    int t0   = blockIdx.x * TT;
    int m    = blockIdx.y * 8 + warp;

    // Stage LL + M once (first chunk's barrier orders them).
    #pragma unroll
    for (int i = tid; i < NV * NV; i += 256) LLs[i] = g_LLd[i];
    #pragma unroll
    for (int i = tid; i < 96 * (NO / 2) / 2; i += 256)
        ((float4*)Ms)[i] = ((const float4*)g_M2)[i];

    ull_t acce[NO / 2], acco[NO / 2];
    #pragma unroll
    for (int oo = 0; oo < NO / 2; oo++) { acce[oo] = 0ull; acco[oo] = 0ull; }

    const float4* xg = (const float4*)(x + ((size_t)b * NC * NV) * NT + t0);

    for (int cc = 0; cc < NCHUNK; cc++) {
        // ---- Fill X chunk: rows (c = cc*4 + r, n), 16 float4 of t each ----
        #pragma unroll
        for (int i = tid; i < CCH * NV * (TT / 4); i += 256) {
            int row = i >> 4, q = i & 15;                 // row = r*24+n
            ((float4*)Xs)[i] = xg[(cc * CCH * NV + row) * (NT / 4) + q];
        }
        __syncthreads();

        // ---- Stage A: (w,v) t-pair accumulation, LL dup from smem ----
        ull_t w2[CCH], v2[CCH];
        #pragma unroll
        for (int c = 0; c < CCH; c++) { w2[c] = 0ull; v2[c] = 0ull; }

        const ull_t* Xs2 = (const ull_t*)Xs;
        #pragma unroll
        for (int n = 0; n < NV; n++) {
            ulonglong2 ll = ((const ulonglong2*)LLs)[n * NV + m];   // (L,L | L2,L2)
            #pragma unroll
            for (int c = 0; c < CCH; c++) {
                ull_t x2 = Xs2[(c * NV + n) * (TT / 2) + lane];
                w2[c] = ffma2(x2, ll.x, w2[c]);
                v2[c] = ffma2(x2, ll.y, v2[c]);
            }
        }
        ull_t xm2[CCH];
        #pragma unroll
        for (int c = 0; c < CCH; c++) xm2[c] = Xs2[(c * NV + m) * (TT / 2) + lane];
        __syncthreads();   // chunk consumed; next fill may overwrite

        // ---- Stage B: o-paired accumulation, x-side dup'd ----
        #pragma unroll
        for (int c = 0; c < CCH; c++) {
            int cg = cc * CCH + c;
            float2 xm_ = unpack2(xm2[c]);
            float2 w_  = unpack2(w2[c]);
            float2 v_  = unpack2(v2[c]);
            ull_t d0e = pack2(xm_.x, xm_.x), d0o = pack2(xm_.y, xm_.y);
            ull_t d1e = pack2(w_.x,  w_.x),  d1o = pack2(w_.y,  w_.y);
            ull_t d2e = pack2(v_.x,  v_.x),  d2o = pack2(v_.y,  v_.y);

            const ulonglong2* M0 = (const ulonglong2*)(Ms + (0 * NC + cg) * (NO / 2));
            const ulonglong2* M1 = (const ulonglong2*)(Ms + (1 * NC + cg) * (NO / 2));
            const ulonglong2* M2p = (const ulonglong2*)(Ms + (2 * NC + cg) * (NO / 2));
            #pragma unroll
            for (int p = 0; p < NO / 4; p++) {            // 2 oo per iter (LDS.128)
                ulonglong2 a  = M0[p];
                ulonglong2 bq = M1[p];
                ulonglong2 cq = M2p[p];
                acce[2 * p]     = ffma2(cq.x, d2e, ffma2(bq.x, d1e, ffma2(a.x, d0e, acce[2 * p])));
                acco[2 * p]     = ffma2(cq.x, d2o, ffma2(bq.x, d1o, ffma2(a.x, d0o, acco[2 * p])));
                acce[2 * p + 1] = ffma2(cq.y, d2e, ffma2(bq.y, d1e, ffma2(a.y, d0e, acce[2 * p + 1])));
                acco[2 * p + 1] = ffma2(cq.y, d2o, ffma2(bq.y, d1o, ffma2(a.y, d0o, acco[2 * p + 1])));
            }
        }
    }

    // ---- Epilogue: transpose (o-pair, t-pair) -> two float2 stores per oo ----
    size_t obase = ((size_t)b * NO * NV) * NT + (size_t)m * NT + t0 + 2 * lane;
    #pragma unroll
    for (int oo = 0; oo < NO / 2; oo++) {
        float2 e = unpack2(acce[oo]);      // (o=2oo, o=2oo+1) at t even
        float2 o_ = unpack2(acco[oo]);     // same at t odd
        *(float2*)&out[obase + (size_t)(2 * oo)     * NV * NT] = make_float2(e.x, o_.x);
        *(float2*)&out[obase + (size_t)(2 * oo + 1) * NV * NT] = make_float2(e.y, o_.y);
    }
}

extern "C" void kernel_launch(void* const* d_in, const int* in_sizes, int n_in,
                              void* d_out, int out_size) {
    const float* x     = (const float*)d_in[0];   // (64,32,24,512)
    const float* adj   = (const float*)d_in[1];   // (24,24)
    const float* Theta = (const float*)d_in[2];   // (3,32,32)
    float* out = (float*)d_out;                   // (64,32,24,512)

    cheb_prep<<<1, 128>>>(adj, Theta);

    dim3 grid(NT / TT, 3, NB);   // 8 t-chunks, 3 m-groups, 64 b = 1536 blocks
    cheb_main<<<grid, 256>>>(x, out);
}